// round 9
// baseline (speedup 1.0000x reference)
#include <cuda_runtime.h>
#include <cuda_bf16.h>
#include <cstdint>

// LightGCN 2-hop smoothing, pull-based SpMM over an on-the-fly CSR.
// Gather payloads in bf16 (dis-weight pre-folded), fp32 accumulation,
// uniform predicated MLP=4 gather loop (no serial tail).
// out = (2*x0 + 2*x1 + x2)/3, x1 = S x0, x2 = S x1, S = D^-1/2 A D^-1/2.

#define EMB 64
#define MAX_NODES 200000
#define MAX_DEDGES 2500000
#define SCAN_B 256
#define MAX_SCAN_BLOCKS 1024   // ceil(200000/256) = 782

__device__ int   g_deg[MAX_NODES];
__device__ float g_dis[MAX_NODES];
__device__ int   g_row[MAX_NODES + 1];
__device__ int   g_cursor[MAX_NODES];
__device__ int   g_bsums[MAX_SCAN_BLOCKS];
__device__ int   g_adj[MAX_DEDGES];
__device__ float g_x1[(size_t)MAX_NODES * EMB];            // fp32 x1 (combine)
__device__ uint2 g_x0h[(size_t)MAX_NODES * (EMB / 4)];     // bf16 dis[s]*x0[s]
__device__ uint2 g_x1h[(size_t)MAX_NODES * (EMB / 4)];     // bf16 dis[s]*x1[s]

__global__ void zero_deg_kernel(int N) {
    int n = blockIdx.x * blockDim.x + threadIdx.x;
    if (n < N) g_deg[n] = 0;
}

__global__ void deg_kernel(const int* __restrict__ u_idx,
                           const int* __restrict__ i_idx,
                           int E, int NU) {
    int e = blockIdx.x * blockDim.x + threadIdx.x;
    if (e < E) {
        atomicAdd(&g_deg[u_idx[e]], 1);
        atomicAdd(&g_deg[NU + i_idx[e]], 1);
    }
}

// ---- scan1: block-local exclusive scan of g_deg into g_row; computes g_dis ----
__global__ void scan1_kernel(int N) {
    __shared__ int warp_tot[SCAN_B / 32];
    int t = threadIdx.x;
    int lane = t & 31;
    int wid = t >> 5;
    int idx = blockIdx.x * SCAN_B + t;
    int v = (idx < N) ? g_deg[idx] : 0;
    if (idx < N) g_dis[idx] = (v > 0) ? rsqrtf((float)v) : 0.0f;

    int s = v;
    #pragma unroll
    for (int off = 1; off < 32; off <<= 1) {
        int n = __shfl_up_sync(0xffffffffu, s, off);
        if (lane >= off) s += n;
    }
    if (lane == 31) warp_tot[wid] = s;
    __syncthreads();
    if (wid == 0) {
        int w = (lane < SCAN_B / 32) ? warp_tot[lane] : 0;
        #pragma unroll
        for (int off = 1; off < 32; off <<= 1) {
            int n = __shfl_up_sync(0xffffffffu, w, off);
            if (lane >= off) w += n;
        }
        if (lane < SCAN_B / 32) warp_tot[lane] = w;
    }
    __syncthreads();
    int base = (wid > 0) ? warp_tot[wid - 1] : 0;
    int incl = base + s;
    if (idx < N) g_row[idx] = incl - v;           // block-local exclusive
    if (t == SCAN_B - 1) g_bsums[blockIdx.x] = incl;
}

// ---- scan_apply: each block reduces bsums[0..bid) itself, applies offset ----
__global__ void scan_apply_kernel(int N, int twoE) {
    __shared__ int red[SCAN_B / 32];
    int t = threadIdx.x;
    int lane = t & 31;
    int wid = t >> 5;

    int sum = 0;
    for (int j = t; j < blockIdx.x; j += SCAN_B) sum += g_bsums[j];
    #pragma unroll
    for (int off = 16; off > 0; off >>= 1)
        sum += __shfl_xor_sync(0xffffffffu, sum, off);
    if (lane == 0) red[wid] = sum;
    __syncthreads();
    if (wid == 0) {
        int w = (lane < SCAN_B / 32) ? red[lane] : 0;
        #pragma unroll
        for (int off = 16; off > 0; off >>= 1)
            w += __shfl_xor_sync(0xffffffffu, w, off);
        if (lane == 0) red[0] = w;
    }
    __syncthreads();
    int offset = red[0];

    int idx = blockIdx.x * SCAN_B + t;
    if (idx < N) {
        int r = g_row[idx] + offset;
        g_row[idx] = r;
        g_cursor[idx] = r;
    }
    if (idx == 0) g_row[N] = twoE;
}

__global__ void fill_kernel(const int* __restrict__ u_idx,
                            const int* __restrict__ i_idx,
                            int E, int NU) {
    int e = blockIdx.x * blockDim.x + threadIdx.x;
    if (e < E) {
        int u = u_idx[e];
        int g = NU + i_idx[e];
        g_adj[atomicAdd(&g_cursor[g], 1)] = u;
        g_adj[atomicAdd(&g_cursor[u], 1)] = g;
    }
}

__device__ __forceinline__ uint2 pack4(float a, float b, float c, float d) {
    uint2 v;
    __nv_bfloat162* h = reinterpret_cast<__nv_bfloat162*>(&v);
    h[0] = __float22bfloat162_rn(make_float2(a, b));
    h[1] = __float22bfloat162_rn(make_float2(c, d));
    return v;
}

// g_x0h[n] = bf16(dis[n] * x0[n]); thread per uint2 chunk (4 dims).
__global__ void conv_kernel(const float* __restrict__ u_emb,
                            const float* __restrict__ i_emb,
                            int N, int NU) {
    size_t tot = (size_t)N * 16;
    size_t stride = (size_t)gridDim.x * blockDim.x;
    for (size_t idx = (size_t)blockIdx.x * blockDim.x + threadIdx.x; idx < tot; idx += stride) {
        int row = (int)(idx >> 4);
        int c   = (int)(idx & 15);
        float dn = g_dis[row];
        const float4* src = (row < NU) ? (const float4*)(u_emb + (size_t)row * EMB)
                                       : (const float4*)(i_emb + (size_t)(row - NU) * EMB);
        float4 a = src[c];
        g_x0h[idx] = pack4(dn * a.x, dn * a.y, dn * a.z, dn * a.w);
    }
}

__device__ __forceinline__ void accum4(float* acc, uint2 v) {
    __nv_bfloat162* h = reinterpret_cast<__nv_bfloat162*>(&v);
    float2 f0 = __bfloat1622float2(h[0]);
    float2 f1 = __bfloat1622float2(h[1]);
    acc[0] += f0.x; acc[1] += f0.y;
    acc[2] += f1.x; acc[3] += f1.y;
}

// ---- pull pass 1: x1 = S x0 (bf16 pre-folded sources) ----
// Warp per node. 16 lanes x uint2 (4 bf16 dims) = 128B row; half-warps take
// alternate slots; uniform loop: 8 slots/step, clamped indices, invalid slots
// zeroed -> 4 gathers in flight per lane every step.
__global__ void pull1_kernel(int N) {
    int warp = (int)(((size_t)blockIdx.x * blockDim.x + threadIdx.x) >> 5);
    int lane = threadIdx.x & 31;
    if (warp >= N) return;

    int half = lane >> 4;
    int q    = lane & 15;

    int start = g_row[warp];
    int end   = g_row[warp + 1];

    float acc[4] = {0.f, 0.f, 0.f, 0.f};

    for (int k = start; k < end; k += 8) {
        int i0 = k + half, i1 = k + 2 + half, i2 = k + 4 + half, i3 = k + 6 + half;
        int lim = end - 1;
        int s0 = g_adj[min(i0, lim)];
        int s1 = g_adj[min(i1, lim)];
        int s2 = g_adj[min(i2, lim)];
        int s3 = g_adj[min(i3, lim)];
        uint2 v0 = g_x0h[(size_t)s0 * 16 + q];
        uint2 v1 = g_x0h[(size_t)s1 * 16 + q];
        uint2 v2 = g_x0h[(size_t)s2 * 16 + q];
        uint2 v3 = g_x0h[(size_t)s3 * 16 + q];
        if (i0 >= end) { v0.x = 0u; v0.y = 0u; }
        if (i1 >= end) { v1.x = 0u; v1.y = 0u; }
        if (i2 >= end) { v2.x = 0u; v2.y = 0u; }
        if (i3 >= end) { v3.x = 0u; v3.y = 0u; }
        accum4(acc, v0);
        accum4(acc, v1);
        accum4(acc, v2);
        accum4(acc, v3);
    }

    #pragma unroll
    for (int i = 0; i < 4; i++)
        acc[i] += __shfl_xor_sync(0xffffffffu, acc[i], 16);

    if (half == 0) {
        float dn = g_dis[warp];
        float x1a = dn * acc[0], x1b = dn * acc[1];
        float x1c = dn * acc[2], x1d = dn * acc[3];
        ((float4*)(g_x1 + (size_t)warp * EMB))[q] = make_float4(x1a, x1b, x1c, x1d);
        g_x1h[(size_t)warp * 16 + q] = pack4(dn * x1a, dn * x1b, dn * x1c, dn * x1d);
    }
}

// ---- pull pass 2 fused with output combine ----
// out[n] = (2*x0[n] + 2*x1[n] + dn * sum_s bf16(dis[s]*x1[s])) / 3
__global__ void pull2_kernel(const float* __restrict__ u_emb,
                             const float* __restrict__ i_emb,
                             float* __restrict__ out,
                             int N, int NU) {
    int warp = (int)(((size_t)blockIdx.x * blockDim.x + threadIdx.x) >> 5);
    int lane = threadIdx.x & 31;
    if (warp >= N) return;

    int half = lane >> 4;
    int q    = lane & 15;

    int start = g_row[warp];
    int end   = g_row[warp + 1];

    float acc[4] = {0.f, 0.f, 0.f, 0.f};

    for (int k = start; k < end; k += 8) {
        int i0 = k + half, i1 = k + 2 + half, i2 = k + 4 + half, i3 = k + 6 + half;
        int lim = end - 1;
        int s0 = g_adj[min(i0, lim)];
        int s1 = g_adj[min(i1, lim)];
        int s2 = g_adj[min(i2, lim)];
        int s3 = g_adj[min(i3, lim)];
        uint2 v0 = g_x1h[(size_t)s0 * 16 + q];
        uint2 v1 = g_x1h[(size_t)s1 * 16 + q];
        uint2 v2 = g_x1h[(size_t)s2 * 16 + q];
        uint2 v3 = g_x1h[(size_t)s3 * 16 + q];
        if (i0 >= end) { v0.x = 0u; v0.y = 0u; }
        if (i1 >= end) { v1.x = 0u; v1.y = 0u; }
        if (i2 >= end) { v2.x = 0u; v2.y = 0u; }
        if (i3 >= end) { v3.x = 0u; v3.y = 0u; }
        accum4(acc, v0);
        accum4(acc, v1);
        accum4(acc, v2);
        accum4(acc, v3);
    }

    #pragma unroll
    for (int i = 0; i < 4; i++)
        acc[i] += __shfl_xor_sync(0xffffffffu, acc[i], 16);

    if (half == 0) {
        float dn = g_dis[warp];
        const float4* x0b = (warp < NU)
            ? (const float4*)(u_emb + (size_t)warp * EMB)
            : (const float4*)(i_emb + (size_t)(warp - NU) * EMB);
        float4 x0v = x0b[q];
        float4 x1v = ((const float4*)(g_x1 + (size_t)warp * EMB))[q];
        const float inv3 = 1.0f / 3.0f;
        float4 o;
        o.x = (2.0f * x0v.x + 2.0f * x1v.x + dn * acc[0]) * inv3;
        o.y = (2.0f * x0v.y + 2.0f * x1v.y + dn * acc[1]) * inv3;
        o.z = (2.0f * x0v.z + 2.0f * x1v.z + dn * acc[2]) * inv3;
        o.w = (2.0f * x0v.w + 2.0f * x1v.w + dn * acc[3]) * inv3;
        ((float4*)(out + (size_t)warp * EMB))[q] = o;
    }
}

extern "C" void kernel_launch(void* const* d_in, const int* in_sizes, int n_in,
                              void* d_out, int out_size) {
    const float* u_emb = (const float*)d_in[0];
    const float* i_emb = (const float*)d_in[1];
    const int*   u_idx = (const int*)d_in[2];
    const int*   i_idx = (const int*)d_in[3];
    float*       out   = (float*)d_out;

    int NU = in_sizes[0] / EMB;
    int NI = in_sizes[1] / EMB;
    int E  = in_sizes[2];
    int N  = NU + NI;

    int nScanBlocks = (N + SCAN_B - 1) / SCAN_B;

    zero_deg_kernel<<<(N + 255) / 256, 256>>>(N);
    deg_kernel<<<(E + 255) / 256, 256>>>(u_idx, i_idx, E, NU);

    scan1_kernel<<<nScanBlocks, SCAN_B>>>(N);
    scan_apply_kernel<<<nScanBlocks, SCAN_B>>>(N, 2 * E);

    fill_kernel<<<(E + 255) / 256, 256>>>(u_idx, i_idx, E, NU);
    conv_kernel<<<2048, 256>>>(u_emb, i_emb, N, NU);

    {
        size_t threads_total = (size_t)N * 32;
        int blocks = (int)((threads_total + 255) / 256);
        pull1_kernel<<<blocks, 256>>>(N);
        pull2_kernel<<<blocks, 256>>>(u_emb, i_emb, out, N, NU);
    }
}

// round 10
// speedup vs baseline: 1.0434x; 1.0434x over previous
#include <cuda_runtime.h>
#include <cstdint>

// LightGCN 2-hop smoothing, pull-based SpMM over an on-the-fly CSR.
// fp32 throughout. Uniform predicated gather loop (MLP=4, no serial tail).
// out = (2*x0 + 2*x1 + x2)/3, x1 = S x0, x2 = S x1, S = D^-1/2 A D^-1/2.

#define EMB 64
#define MAX_NODES 200000
#define MAX_DEDGES 2500000
#define SCAN_B 256
#define MAX_SCAN_BLOCKS 1024   // ceil(200000/256) = 782

__device__ int   g_deg[MAX_NODES];
__device__ float g_dis[MAX_NODES];
__device__ int   g_row[MAX_NODES + 1];
__device__ int   g_cursor[MAX_NODES];
__device__ int   g_bsums[MAX_SCAN_BLOCKS];
__device__ int   g_adj[MAX_DEDGES];
__device__ float g_x1[(size_t)MAX_NODES * EMB];

__global__ void zero_deg_kernel(int N) {
    int n = blockIdx.x * blockDim.x + threadIdx.x;
    if (n < N) g_deg[n] = 0;
}

// 4 edges per thread via int4 loads.
__global__ void deg_kernel(const int* __restrict__ u_idx,
                           const int* __restrict__ i_idx,
                           int E, int NU) {
    int e4 = blockIdx.x * blockDim.x + threadIdx.x;
    int base = e4 * 4;
    if (base + 3 < E) {
        int4 u = ((const int4*)u_idx)[e4];
        int4 i = ((const int4*)i_idx)[e4];
        atomicAdd(&g_deg[u.x], 1);
        atomicAdd(&g_deg[u.y], 1);
        atomicAdd(&g_deg[u.z], 1);
        atomicAdd(&g_deg[u.w], 1);
        atomicAdd(&g_deg[NU + i.x], 1);
        atomicAdd(&g_deg[NU + i.y], 1);
        atomicAdd(&g_deg[NU + i.z], 1);
        atomicAdd(&g_deg[NU + i.w], 1);
    } else {
        for (int e = base; e < E; e++) {
            atomicAdd(&g_deg[u_idx[e]], 1);
            atomicAdd(&g_deg[NU + i_idx[e]], 1);
        }
    }
}

// ---- scan1: block-local exclusive scan of g_deg into g_row; computes g_dis ----
__global__ void scan1_kernel(int N) {
    __shared__ int warp_tot[SCAN_B / 32];
    int t = threadIdx.x;
    int lane = t & 31;
    int wid = t >> 5;
    int idx = blockIdx.x * SCAN_B + t;
    int v = (idx < N) ? g_deg[idx] : 0;
    if (idx < N) g_dis[idx] = (v > 0) ? rsqrtf((float)v) : 0.0f;

    int s = v;
    #pragma unroll
    for (int off = 1; off < 32; off <<= 1) {
        int n = __shfl_up_sync(0xffffffffu, s, off);
        if (lane >= off) s += n;
    }
    if (lane == 31) warp_tot[wid] = s;
    __syncthreads();
    if (wid == 0) {
        int w = (lane < SCAN_B / 32) ? warp_tot[lane] : 0;
        #pragma unroll
        for (int off = 1; off < 32; off <<= 1) {
            int n = __shfl_up_sync(0xffffffffu, w, off);
            if (lane >= off) w += n;
        }
        if (lane < SCAN_B / 32) warp_tot[lane] = w;
    }
    __syncthreads();
    int base = (wid > 0) ? warp_tot[wid - 1] : 0;
    int incl = base + s;
    if (idx < N) g_row[idx] = incl - v;           // block-local exclusive
    if (t == SCAN_B - 1) g_bsums[blockIdx.x] = incl;
}

// ---- scan_apply: each block reduces bsums[0..bid) itself, applies offset ----
__global__ void scan_apply_kernel(int N, int twoE) {
    __shared__ int red[SCAN_B / 32];
    int t = threadIdx.x;
    int lane = t & 31;
    int wid = t >> 5;

    int sum = 0;
    for (int j = t; j < blockIdx.x; j += SCAN_B) sum += g_bsums[j];
    #pragma unroll
    for (int off = 16; off > 0; off >>= 1)
        sum += __shfl_xor_sync(0xffffffffu, sum, off);
    if (lane == 0) red[wid] = sum;
    __syncthreads();
    if (wid == 0) {
        int w = (lane < SCAN_B / 32) ? red[lane] : 0;
        #pragma unroll
        for (int off = 16; off > 0; off >>= 1)
            w += __shfl_xor_sync(0xffffffffu, w, off);
        if (lane == 0) red[0] = w;
    }
    __syncthreads();
    int offset = red[0];

    int idx = blockIdx.x * SCAN_B + t;
    if (idx < N) {
        int r = g_row[idx] + offset;
        g_row[idx] = r;
        g_cursor[idx] = r;
    }
    if (idx == 0) g_row[N] = twoE;
}

// 4 edges per thread via int4 loads.
__global__ void fill_kernel(const int* __restrict__ u_idx,
                            const int* __restrict__ i_idx,
                            int E, int NU) {
    int e4 = blockIdx.x * blockDim.x + threadIdx.x;
    int base = e4 * 4;
    if (base + 3 < E) {
        int4 u = ((const int4*)u_idx)[e4];
        int4 i = ((const int4*)i_idx)[e4];
        int gx = NU + i.x, gy = NU + i.y, gz = NU + i.z, gw = NU + i.w;
        g_adj[atomicAdd(&g_cursor[gx], 1)] = u.x;
        g_adj[atomicAdd(&g_cursor[gy], 1)] = u.y;
        g_adj[atomicAdd(&g_cursor[gz], 1)] = u.z;
        g_adj[atomicAdd(&g_cursor[gw], 1)] = u.w;
        g_adj[atomicAdd(&g_cursor[u.x], 1)] = gx;
        g_adj[atomicAdd(&g_cursor[u.y], 1)] = gy;
        g_adj[atomicAdd(&g_cursor[u.z], 1)] = gz;
        g_adj[atomicAdd(&g_cursor[u.w], 1)] = gw;
    } else {
        for (int e = base; e < E; e++) {
            int u = u_idx[e];
            int g = NU + i_idx[e];
            g_adj[atomicAdd(&g_cursor[g], 1)] = u;
            g_adj[atomicAdd(&g_cursor[u], 1)] = g;
        }
    }
}

// ---- pull pass 1: x1 = S x0 ----
// Warp per node. Half-warps (16 lanes, float4 each = 256B row) take alternate
// neighbor slots. Uniform loop: 8 slots/step, indices clamped, weights zeroed
// when out of range -> MLP=4 every step, no serial tail.
__global__ void pull1_kernel(const float* __restrict__ u_emb,
                             const float* __restrict__ i_emb,
                             int N, int NU) {
    int warp = (int)(((size_t)blockIdx.x * blockDim.x + threadIdx.x) >> 5);
    int lane = threadIdx.x & 31;
    if (warp >= N) return;

    int half = lane >> 4;
    int q    = lane & 15;

    int start = g_row[warp];
    int end   = g_row[warp + 1];

    float4 acc = make_float4(0.f, 0.f, 0.f, 0.f);

    for (int k = start; k < end; k += 8) {
        int i0 = k + half, i1 = k + 2 + half, i2 = k + 4 + half, i3 = k + 6 + half;
        int lim = end - 1;
        int s0 = g_adj[min(i0, lim)];
        int s1 = g_adj[min(i1, lim)];
        int s2 = g_adj[min(i2, lim)];
        int s3 = g_adj[min(i3, lim)];
        float w0 = (i0 < end) ? g_dis[s0] : 0.f;
        float w1 = (i1 < end) ? g_dis[s1] : 0.f;
        float w2 = (i2 < end) ? g_dis[s2] : 0.f;
        float w3 = (i3 < end) ? g_dis[s3] : 0.f;
        const float4* p0 = (s0 < NU) ? (const float4*)(u_emb + (size_t)s0 * EMB)
                                     : (const float4*)(i_emb + (size_t)(s0 - NU) * EMB);
        const float4* p1 = (s1 < NU) ? (const float4*)(u_emb + (size_t)s1 * EMB)
                                     : (const float4*)(i_emb + (size_t)(s1 - NU) * EMB);
        const float4* p2 = (s2 < NU) ? (const float4*)(u_emb + (size_t)s2 * EMB)
                                     : (const float4*)(i_emb + (size_t)(s2 - NU) * EMB);
        const float4* p3 = (s3 < NU) ? (const float4*)(u_emb + (size_t)s3 * EMB)
                                     : (const float4*)(i_emb + (size_t)(s3 - NU) * EMB);
        float4 v0 = p0[q], v1 = p1[q], v2 = p2[q], v3 = p3[q];
        acc.x += w0 * v0.x + w1 * v1.x + w2 * v2.x + w3 * v3.x;
        acc.y += w0 * v0.y + w1 * v1.y + w2 * v2.y + w3 * v3.y;
        acc.z += w0 * v0.z + w1 * v1.z + w2 * v2.z + w3 * v3.z;
        acc.w += w0 * v0.w + w1 * v1.w + w2 * v2.w + w3 * v3.w;
    }

    acc.x += __shfl_xor_sync(0xffffffffu, acc.x, 16);
    acc.y += __shfl_xor_sync(0xffffffffu, acc.y, 16);
    acc.z += __shfl_xor_sync(0xffffffffu, acc.z, 16);
    acc.w += __shfl_xor_sync(0xffffffffu, acc.w, 16);

    if (half == 0) {
        float dn = g_dis[warp];
        ((float4*)(g_x1 + (size_t)warp * EMB))[q] =
            make_float4(dn * acc.x, dn * acc.y, dn * acc.z, dn * acc.w);
    }
}

// ---- pull pass 2 fused with output combine ----
// out[n] = (2*x0[n] + 2*x1[n] + dis[n]*sum dis[s]*x1[s]) / 3
__global__ void pull2_kernel(const float* __restrict__ u_emb,
                             const float* __restrict__ i_emb,
                             float* __restrict__ out,
                             int N, int NU) {
    int warp = (int)(((size_t)blockIdx.x * blockDim.x + threadIdx.x) >> 5);
    int lane = threadIdx.x & 31;
    if (warp >= N) return;

    int half = lane >> 4;
    int q    = lane & 15;

    int start = g_row[warp];
    int end   = g_row[warp + 1];

    float4 acc = make_float4(0.f, 0.f, 0.f, 0.f);

    for (int k = start; k < end; k += 8) {
        int i0 = k + half, i1 = k + 2 + half, i2 = k + 4 + half, i3 = k + 6 + half;
        int lim = end - 1;
        int s0 = g_adj[min(i0, lim)];
        int s1 = g_adj[min(i1, lim)];
        int s2 = g_adj[min(i2, lim)];
        int s3 = g_adj[min(i3, lim)];
        float w0 = (i0 < end) ? g_dis[s0] : 0.f;
        float w1 = (i1 < end) ? g_dis[s1] : 0.f;
        float w2 = (i2 < end) ? g_dis[s2] : 0.f;
        float w3 = (i3 < end) ? g_dis[s3] : 0.f;
        float4 v0 = ((const float4*)(g_x1 + (size_t)s0 * EMB))[q];
        float4 v1 = ((const float4*)(g_x1 + (size_t)s1 * EMB))[q];
        float4 v2 = ((const float4*)(g_x1 + (size_t)s2 * EMB))[q];
        float4 v3 = ((const float4*)(g_x1 + (size_t)s3 * EMB))[q];
        acc.x += w0 * v0.x + w1 * v1.x + w2 * v2.x + w3 * v3.x;
        acc.y += w0 * v0.y + w1 * v1.y + w2 * v2.y + w3 * v3.y;
        acc.z += w0 * v0.z + w1 * v1.z + w2 * v2.z + w3 * v3.z;
        acc.w += w0 * v0.w + w1 * v1.w + w2 * v2.w + w3 * v3.w;
    }

    acc.x += __shfl_xor_sync(0xffffffffu, acc.x, 16);
    acc.y += __shfl_xor_sync(0xffffffffu, acc.y, 16);
    acc.z += __shfl_xor_sync(0xffffffffu, acc.z, 16);
    acc.w += __shfl_xor_sync(0xffffffffu, acc.w, 16);

    if (half == 0) {
        float dn = g_dis[warp];
        const float4* x0b = (warp < NU)
            ? (const float4*)(u_emb + (size_t)warp * EMB)
            : (const float4*)(i_emb + (size_t)(warp - NU) * EMB);
        float4 x0v = x0b[q];
        float4 x1v = ((const float4*)(g_x1 + (size_t)warp * EMB))[q];
        const float inv3 = 1.0f / 3.0f;
        float4 o;
        o.x = (2.0f * x0v.x + 2.0f * x1v.x + dn * acc.x) * inv3;
        o.y = (2.0f * x0v.y + 2.0f * x1v.y + dn * acc.y) * inv3;
        o.z = (2.0f * x0v.z + 2.0f * x1v.z + dn * acc.z) * inv3;
        o.w = (2.0f * x0v.w + 2.0f * x1v.w + dn * acc.w) * inv3;
        ((float4*)(out + (size_t)warp * EMB))[q] = o;
    }
}

extern "C" void kernel_launch(void* const* d_in, const int* in_sizes, int n_in,
                              void* d_out, int out_size) {
    const float* u_emb = (const float*)d_in[0];
    const float* i_emb = (const float*)d_in[1];
    const int*   u_idx = (const int*)d_in[2];
    const int*   i_idx = (const int*)d_in[3];
    float*       out   = (float*)d_out;

    int NU = in_sizes[0] / EMB;
    int NI = in_sizes[1] / EMB;
    int E  = in_sizes[2];
    int N  = NU + NI;

    int nScanBlocks = (N + SCAN_B - 1) / SCAN_B;
    int nEdge4 = (E + 3) / 4;

    zero_deg_kernel<<<(N + 255) / 256, 256>>>(N);
    deg_kernel<<<(nEdge4 + 255) / 256, 256>>>(u_idx, i_idx, E, NU);

    scan1_kernel<<<nScanBlocks, SCAN_B>>>(N);
    scan_apply_kernel<<<nScanBlocks, SCAN_B>>>(N, 2 * E);

    fill_kernel<<<(nEdge4 + 255) / 256, 256>>>(u_idx, i_idx, E, NU);

    {
        size_t threads_total = (size_t)N * 32;
        int blocks = (int)((threads_total + 255) / 256);
        pull1_kernel<<<blocks, 256>>>(u_emb, i_emb, N, NU);
        pull2_kernel<<<blocks, 256>>>(u_emb, i_emb, out, N, NU);
    }
}